// round 14
// baseline (speedup 1.0000x reference)
#include <cuda_runtime.h>
#include <float.h>
#include <math.h>
#include <stdint.h>

#define BB 8
#define DD 256
#define MEMN 131072
#define CWN 64
#define RR 4
#define KK 4
#define TKL 8
#define CC 25
#define DELTA_F 0.005f
#define EPS_F 1e-6f

#define NBLK 64
#define ROWS_PER_BLK (MEMN / NBLK)   // 2048
#define UMB 16
#define UMCH (MEMN / UMB)            // 8192
#define SETUPB BB

// ---------------- device scratch ----------------
__device__ float g_q[BB][DD];
__device__ float g_visnew[BB][CC][CWN];
__device__ float g_relnew[BB][CC];
__device__ int   g_fp[BB][KK];
__device__ int   g_bp[BB][KK];
__device__ __align__(16) float g_bv[BB][RR][NBLK][KK];
__device__ __align__(16) int   g_bi[BB][RR][NBLK][KK];
__device__ float g_uv[UMB];
__device__ int   g_ui[UMB];

// ---------------- helpers ----------------
__device__ __forceinline__ float d4(float4 a, float4 b, float acc) {
    acc = fmaf(a.x, b.x, acc);
    acc = fmaf(a.y, b.y, acc);
    acc = fmaf(a.z, b.z, acc);
    acc = fmaf(a.w, b.w, acc);
    return acc;
}

// top-4 insertion; larger value wins, ties -> lower index (jax.lax.top_k)
__device__ __forceinline__ void ins4s(float s, int m,
    float &v0, int &i0, float &v1, int &i1,
    float &v2, int &i2, float &v3, int &i3)
{
    if (!((s > v3) || (s == v3 && m < i3))) return;
    v3 = s; i3 = m;
    if ((v3 > v2) || (v3 == v2 && i3 < i2)) { float tv=v2; int ti=i2; v2=v3; i2=i3; v3=tv; i3=ti; }
    if ((v2 > v1) || (v2 == v1 && i2 < i1)) { float tv=v1; int ti=i1; v1=v2; i1=i2; v2=tv; i2=ti; }
    if ((v1 > v0) || (v1 == v0 && i1 < i0)) { float tv=v0; int ti=i0; v0=v1; i0=i1; v1=tv; i1=ti; }
}

__device__ __forceinline__ float sig_(float x) { return 1.f / (1.f + expf(-x)); }

// ============================================================================
// K0: read_query GEMM, 64 blocks (8 output-chunks x 8 batches), 256 threads.
// ============================================================================
__global__ void __launch_bounds__(256) k0_q(
    const float* __restrict__ xi,
    const float* __restrict__ W_rq,
    const float* __restrict__ b_rq)
{
    int b  = blockIdx.x >> 3;
    int oc = blockIdx.x & 7;
    int t  = threadIdx.x;
    int dc = t >> 5, o = t & 31;
    int og = oc * 32 + o;

    __shared__ float xs[DD];
    __shared__ float psum[8][32];

    xs[t] = xi[b * DD + t];
    __syncthreads();

    const float* W = W_rq + (size_t)(dc * 32) * 256 + og;
    const float* x = xs + dc * 32;
    float a0 = 0.f, a1 = 0.f, a2 = 0.f, a3 = 0.f;
    #pragma unroll
    for (int d = 0; d < 32; d += 4) {
        a0 = fmaf(x[d + 0], __ldg(&W[(d + 0) * 256]), a0);
        a1 = fmaf(x[d + 1], __ldg(&W[(d + 1) * 256]), a1);
        a2 = fmaf(x[d + 2], __ldg(&W[(d + 2) * 256]), a2);
        a3 = fmaf(x[d + 3], __ldg(&W[(d + 3) * 256]), a3);
    }
    psum[dc][o] = (a0 + a1) + (a2 + a3);
    __syncthreads();

    if (t < 32) {
        float s = b_rq[oc * 32 + t];
        #pragma unroll
        for (int c = 0; c < 8; c++) s += psum[c][t];
        g_q[b][oc * 32 + t] = s;
    }
}

// ============================================================================
// K2: 512 scan + 16 argmin + 8 setup blocks.
//     Scan: q in SMEM (frees ~32 regs -> higher occupancy), coalesced
//     column-split, fold-before-shuffle, unroll 4.
// ============================================================================
__global__ void __launch_bounds__(256) k2_scan(
    const float* __restrict__ memv,
    const float* __restrict__ usage,
    const int*   __restrict__ rp,
    const float* __restrict__ xi,
    const float* __restrict__ visible_memory,
    const float* __restrict__ link_matrix,
    const float* __restrict__ rev_link_matrix,
    const float* __restrict__ precedence,
    const float* __restrict__ read_weights,
    const float* __restrict__ write_weights,
    const float* __restrict__ W_wv, const float* __restrict__ b_wv,
    const float* __restrict__ W_ig, const float* __restrict__ b_ig,
    const float* __restrict__ W_wg, const float* __restrict__ b_wg)
{
    int t = threadIdx.x;

    // ========================= SETUP BLOCKS =========================
    if (blockIdx.x >= BB * NBLK + UMB) {
        int b = blockIdx.x - (BB * NBLK + UMB);

        __shared__ float xs[DD];
        __shared__ float pwv[4][CWN];
        __shared__ float pig[4][CC];
        __shared__ float pwg[32];
        __shared__ float wv_s[CWN];
        __shared__ float ig_s[CC];
        __shared__ float wg_s;
        __shared__ int   rp_s[CC];
        __shared__ float rw_s[CC], rel_s[CC], u_s[CC], imin_s[CC], wwnew_s[CC];
        __shared__ float minrel_s;
        __shared__ float fw_s[TKL], bw_s[TKL];

        xs[t] = xi[b * DD + t];
        if (t < CC) rp_s[t] = rp[b * CC + t];
        __syncthreads();

        bool hasE = (t >= 128 && t < 128 + CC);
        float e_rw = 0.f, e_ww = 0.f, e_rel = 0.f;
        if (hasE) {
            int p = rp_s[t - 128];
            e_rw  = __ldg(&read_weights [(size_t)b * MEMN + p]);
            e_ww  = __ldg(&write_weights[(size_t)b * MEMN + p]);
            e_rel = __ldg(&usage        [(size_t)b * MEMN + p]);
        }
        bool hasL = (t >= 160 && t < 160 + TKL);
        float l_wwm = 0.f, l_wwtp = 0.f, l_rwtp = 0.f, l_lk = 0.f, l_rl = 0.f, l_pr = 0.f;
        if (hasL) {
            int m = t - 160;
            int tp = rp_s[RR * KK + m];
            l_wwm  = __ldg(&write_weights  [(size_t)b * MEMN + m]);
            l_wwtp = __ldg(&write_weights  [(size_t)b * MEMN + tp]);
            l_rwtp = __ldg(&read_weights   [(size_t)b * MEMN + tp]);
            l_lk   = __ldg(&link_matrix    [((size_t)b * MEMN + m) * TKL + m]);
            l_rl   = __ldg(&rev_link_matrix[((size_t)b * MEMN + m) * TKL + m]);
            l_pr   = __ldg(&precedence     [b * TKL + m]);
        }

        {
            int o = t & 63, c = t >> 6;
            const float* W = W_wv + (size_t)(c * 64) * CWN + o;
            const float* x = xs + c * 64;
            float a0 = 0.f, a1 = 0.f, a2 = 0.f, a3 = 0.f;
            #pragma unroll 4
            for (int d = 0; d < 64; d += 4) {
                a0 = fmaf(x[d + 0], W[(d + 0) * CWN], a0);
                a1 = fmaf(x[d + 1], W[(d + 1) * CWN], a1);
                a2 = fmaf(x[d + 2], W[(d + 2) * CWN], a2);
                a3 = fmaf(x[d + 3], W[(d + 3) * CWN], a3);
            }
            pwv[c][o] = (a0 + a1) + (a2 + a3);
        }
        if (t < 100) {
            int o = t % CC, c = t / CC;
            const float* W = W_ig + (size_t)(c * 64) * CC + o;
            const float* x = xs + c * 64;
            float a0 = 0.f, a1 = 0.f;
            #pragma unroll 4
            for (int d = 0; d < 64; d += 2) {
                a0 = fmaf(x[d + 0], W[(d + 0) * CC], a0);
                a1 = fmaf(x[d + 1], W[(d + 1) * CC], a1);
            }
            pig[c][o] = a0 + a1;
        }
        if (t >= 100 && t < 132) {
            int u = t - 100;
            float a = 0.f;
            #pragma unroll
            for (int d = 0; d < 8; d++)
                a = fmaf(xs[u * 8 + d], __ldg(&W_wg[u * 8 + d]), a);
            pwg[u] = a;
        }
        if (hasE) {
            int c = t - 128;
            rw_s[c]  = e_rw;
            rel_s[c] = e_rel;
            u_s[c]   = (e_rw + e_ww > DELTA_F) ? 1.f : 0.f;
        }
        __syncthreads();

        if (t < CWN) {
            wv_s[t] = b_wv[t] + ((pwv[0][t] + pwv[1][t]) + (pwv[2][t] + pwv[3][t]));
        } else if (t < CWN + CC) {
            int o = t - CWN;
            ig_s[o] = sig_(b_ig[o] + ((pig[0][o] + pig[1][o]) + (pig[2][o] + pig[3][o])));
        } else if (t == CWN + CC) {
            float s = b_wg[0];
            #pragma unroll
            for (int u = 0; u < 32; u++) s += pwg[u];
            wg_s = sig_(s);
        } else if (t == 96) {
            float mn = rel_s[0];
            for (int c = 1; c < CC; c++) mn = fminf(mn, rel_s[c]);
            minrel_s = mn;
        }
        __syncthreads();

        if (t < CC) {
            float Imin = (rel_s[t] == minrel_s) ? 1.f : 0.f;
            imin_s[t] = Imin;
            float u = u_s[t], rel = rel_s[t];
            g_relnew[b][t] = (1.f - rel) * u + rel * (1.f - u);
            wwnew_s[t] = wg_s * (ig_s[t] * rw_s[t] + (1.f - ig_s[t]) * Imin);
        }
        __syncthreads();

        for (int e = t; e < CC * CWN; e += 256) {
            int c = e / CWN, k = e % CWN;
            float v = visible_memory[((size_t)b * CC + c) * CWN + k];
            g_visnew[b][c][k] = v * (1.f - imin_s[c]) + wwnew_s[c] * wv_s[k];
        }

        if (hasL) {
            int m = t - 160;
            float wwf = l_wwm;
            for (int c = 0; c < CC; c++) if (rp_s[c] == m) wwf = wwnew_s[c];
            int tp = rp_s[RR * KK + m];
            float tw = l_wwtp;
            for (int c = 0; c < CC; c++) if (rp_s[c] == tp) tw = wwnew_s[c];
            float pd = 0.f;
            for (int j = 0; j < TKL; j++)
                if (rp_s[RR * KK + j] == m) pd = __ldg(&precedence[b * TKL + j]);
            float Ld = (1.f - wwf) * l_lk + wwf * l_pr;
            float Rd = (1.f - tw ) * l_rl + tw  * pd;
            fw_s[m] = Ld * l_rwtp;
            bw_s[m] = Rd * l_rwtp;
        }
        __syncthreads();

        if (t == 0) {
            bool used[TKL];
            for (int m = 0; m < TKL; m++) used[m] = false;
            for (int k = 0; k < KK; k++) {
                int best = -1;
                for (int m = 0; m < TKL; m++)
                    if (!used[m] && (best < 0 || fw_s[m] > fw_s[best])) best = m;
                used[best] = true;
                g_fp[b][k] = best;
            }
            for (int m = 0; m < TKL; m++) used[m] = false;
            for (int k = 0; k < KK; k++) {
                int best = -1;
                for (int m = 0; m < TKL; m++)
                    if (!used[m] && (best < 0 || bw_s[m] > bw_s[best])) best = m;
                used[best] = true;
                g_bp[b][k] = best;
            }
        }
        return;
    }

    // ========================= ARGMIN BLOCKS =========================
    if (blockIdx.x >= BB * NBLK) {
        int ib = blockIdx.x - BB * NBLK;
        __shared__ int   rp0[CC];
        __shared__ float svv[256];
        __shared__ int   sii[256];
        if (t < CC) rp0[t] = rp[t];
        __syncthreads();
        float bv = FLT_MAX; int bi = 0x7fffffff;
        int base = ib * UMCH;
        for (int j = t; j < UMCH; j += 256) {
            int idx = base + j;
            float v = __ldcs(&usage[idx]);
            bool masked = false;
            #pragma unroll
            for (int c = 0; c < CC; c++) masked |= (rp0[c] == idx);
            if (!masked && (v < bv || (v == bv && idx < bi))) { bv = v; bi = idx; }
        }
        svv[t] = bv; sii[t] = bi;
        __syncthreads();
        for (int s = 128; s > 0; s >>= 1) {
            if (t < s) {
                if (svv[t+s] < svv[t] || (svv[t+s] == svv[t] && sii[t+s] < sii[t])) {
                    svv[t] = svv[t+s]; sii[t] = sii[t+s];
                }
            }
            __syncthreads();
        }
        if (t == 0) { g_uv[ib] = svv[0]; g_ui[ib] = sii[0]; }
        return;
    }

    // ========================= SCAN BLOCKS =========================
    int b   = blockIdx.x >> 6;
    int blk = blockIdx.x & 63;
    int rowbase = blk * ROWS_PER_BLK;
    int lane = t & 31, w = t >> 5;
    int sub = lane & 7, grp = lane >> 3;

    __shared__ __align__(16) float qsm[DD];
    __shared__ int   ns;
    __shared__ int   srow[CC];
    __shared__ float msv[RR][128];
    __shared__ int   msi[RR][128];
    if (t == 0) ns = 0;
    if (t < DD) qsm[t] = g_q[b][t];
    __syncthreads();
    if (t < CC) {
        int p = rp[b * CC + t];
        if (p >= rowbase && p < rowbase + ROWS_PER_BLK) {
            int k = atomicAdd(&ns, 1);
            srow[k] = p;
        }
    }
    __syncthreads();
    int nspec = ns;

    float tv0 = -FLT_MAX, tv1 = -FLT_MAX, tv2 = -FLT_MAX, tv3 = -FLT_MAX;
    int   ti0 = 0x7fffffff, ti1 = 0x7fffffff, ti2 = 0x7fffffff, ti3 = 0x7fffffff;

    const float4* basep = (const float4*)(memv + (size_t)b * MEMN * CWN);
    const float4* qp = (const float4*)qsm;   // q[r*16 + j]
    #pragma unroll 4
    for (int it = 0; it < ROWS_PER_BLK / 32; it++) {
        int row = rowbase + it * 32 + w * 4 + grp;
        const float4* p = basep + (size_t)row * 16;
        float4 a0 = __ldcs(p + sub);
        float4 a1 = __ldcs(p + 8 + sub);

        float sq = d4(a0, a0, 0.f); sq = d4(a1, a1, sq);
        float dt0 = d4(a0, qp[sub],      0.f); dt0 = d4(a1, qp[8 + sub],  dt0);
        float dt1 = d4(a0, qp[16 + sub], 0.f); dt1 = d4(a1, qp[24 + sub], dt1);
        float dt2 = d4(a0, qp[32 + sub], 0.f); dt2 = d4(a1, qp[40 + sub], dt2);
        float dt3 = d4(a0, qp[48 + sub], 0.f); dt3 = d4(a1, qp[56 + sub], dt3);

        float v0 = fmaf(2.f, dt0, -sq);
        float v1 = fmaf(2.f, dt1, -sq);
        float v2 = fmaf(2.f, dt2, -sq);
        float v3 = fmaf(2.f, dt3, -sq);

        #pragma unroll
        for (int m = 4; m >= 1; m >>= 1) {
            v0 += __shfl_xor_sync(0xffffffffu, v0, m);
            v1 += __shfl_xor_sync(0xffffffffu, v1, m);
            v2 += __shfl_xor_sync(0xffffffffu, v2, m);
            v3 += __shfl_xor_sync(0xffffffffu, v3, m);
        }

        if (sub < RR) {
            float s = (sub == 0) ? v0 : (sub == 1) ? v1 : (sub == 2) ? v2 : v3;
            for (int j = 0; j < nspec; j++) if (srow[j] == row) s = -FLT_MAX;
            ins4s(s, row, tv0, ti0, tv1, ti1, tv2, ti2, tv3, ti3);
        }
    }

    if (sub < RR) {
        int slot = w * 16 + grp * 4;
        msv[sub][slot + 0] = tv0; msi[sub][slot + 0] = ti0;
        msv[sub][slot + 1] = tv1; msi[sub][slot + 1] = ti1;
        msv[sub][slot + 2] = tv2; msi[sub][slot + 2] = ti2;
        msv[sub][slot + 3] = tv3; msi[sub][slot + 3] = ti3;
    }
    __syncthreads();

    if (t < RR) {
        float v0 = -FLT_MAX, v1 = -FLT_MAX, v2 = -FLT_MAX, v3 = -FLT_MAX;
        int   i0 = 0x7fffffff, i1 = 0x7fffffff, i2 = 0x7fffffff, i3 = 0x7fffffff;
        for (int j = 0; j < 128; j++)
            ins4s(msv[t][j], msi[t][j], v0, i0, v1, i1, v2, i2, v3, i3);
        g_bv[b][t][blk][0] = v0; g_bi[b][t][blk][0] = i0;
        g_bv[b][t][blk][1] = v1; g_bi[b][t][blk][1] = i1;
        g_bv[b][t][blk][2] = v2; g_bi[b][t][blk][2] = i2;
        g_bv[b][t][blk][3] = v3; g_bi[b][t][blk][3] = i3;
    }
}

// ============================================================================
// K3: fully warp-parallel finish; candidate loads hoisted to kernel start.
// ============================================================================
__global__ void __launch_bounds__(512) k3_finish(
    const float* __restrict__ memv,
    const int*   __restrict__ rp,
    float* __restrict__ out)
{
    int b = blockIdx.x;
    int t = threadIdx.x;
    int lane = t & 31, wid = t >> 5;

    __shared__ float q[DD];
    __shared__ float visn[CC][CWN];
    __shared__ float qn[RR];
    __shared__ int   rps[CC];
    __shared__ int   rp0s[CC];
    __shared__ int   valid[CC];
    __shared__ float specs[RR][CC];
    __shared__ int   pos[CC];
    __shared__ int   maxlen_s;
    __shared__ int   rowsrc[CC];
    __shared__ float vis[CC][CWN];
    __shared__ float sim[RR][CC];
    __shared__ float swx[RR][CC];

    float4 fv0, fv1; int4 iv0, iv1;
    if (wid < RR) {
        const float4* pv = (const float4*)&g_bv[b][wid][0][0];
        const int4*   pi = (const int4*)&g_bi[b][wid][0][0];
        fv0 = pv[2 * lane]; fv1 = pv[2 * lane + 1];
        iv0 = pi[2 * lane]; iv1 = pi[2 * lane + 1];
    }

    if (t < DD) q[t] = g_q[b][t];
    if (t >= 256 && t < 256 + CC) rps[t - 256] = rp[b * CC + (t - 256)];
    if (t >= 288 && t < 288 + CC) rp0s[t - 288] = rp[t - 288];
    for (int e = t; e < CC * CWN; e += 512)
        visn[e >> 6][e & 63] = g_visnew[b][e >> 6][e & 63];
    __syncthreads();

    if (wid < RR) {
        float a0 = q[wid * 64 + lane], a1 = q[wid * 64 + 32 + lane];
        float s = a0 * a0 + a1 * a1;
        #pragma unroll
        for (int off = 16; off >= 1; off >>= 1)
            s += __shfl_down_sync(0xffffffffu, s, off);
        if (lane == 0) qn[wid] = 1.f / (sqrtf(s) + EPS_F);
    }
    if (wid < 15) {
        for (int k = wid; k < RR * CC; k += 15) {
            int c = k / RR, r = k % RR;
            float a0 = visn[c][lane], a1 = visn[c][lane + 32];
            float dt = a0 * q[r * 64 + lane] + a1 * q[r * 64 + 32 + lane];
            float sq = a0 * a0 + a1 * a1;
            #pragma unroll
            for (int off = 16; off >= 1; off >>= 1) {
                dt += __shfl_down_sync(0xffffffffu, dt, off);
                sq += __shfl_down_sync(0xffffffffu, sq, off);
            }
            if (lane == 0) specs[r][c] = 2.f * dt - sq;
        }
    } else {
        float cv_ = FLT_MAX; int cix = 0x7fffffff;
        if (lane < UMB) { cv_ = g_uv[lane]; cix = g_ui[lane]; }
        if (lane < CC) {
            int p0 = rp0s[lane];
            bool last = true;
            for (int c2 = lane + 1; c2 < CC; c2++) if (rp0s[c2] == p0) last = false;
            if (last) {
                float v = g_relnew[0][lane];
                if (v < cv_ || (v == cv_ && p0 < cix)) { cv_ = v; cix = p0; }
            }
        }
        #pragma unroll
        for (int off = 16; off >= 1; off >>= 1) {
            float ov = __shfl_down_sync(0xffffffffu, cv_, off);
            int   oi = __shfl_down_sync(0xffffffffu, cix, off);
            if (lane < off && (ov < cv_ || (ov == cv_ && oi < cix))) { cv_ = ov; cix = oi; }
        }
        if (lane == 0) maxlen_s = cix;
    }
    if (t >= 448 && t < 448 + CC) {
        int c = t - 448;
        int v = 1;
        for (int c2 = c + 1; c2 < CC; c2++) if (rps[c2] == rps[c]) v = 0;
        valid[c] = v;
    }
    __syncthreads();

    if (wid < RR) {
        int r = wid;
        float v0 = -FLT_MAX, v1 = -FLT_MAX, v2 = -FLT_MAX, v3 = -FLT_MAX;
        int   i0 = 0x7fffffff, i1 = 0x7fffffff, i2 = 0x7fffffff, i3 = 0x7fffffff;
        ins4s(fv0.x, iv0.x, v0,i0,v1,i1,v2,i2,v3,i3);
        ins4s(fv0.y, iv0.y, v0,i0,v1,i1,v2,i2,v3,i3);
        ins4s(fv0.z, iv0.z, v0,i0,v1,i1,v2,i2,v3,i3);
        ins4s(fv0.w, iv0.w, v0,i0,v1,i1,v2,i2,v3,i3);
        ins4s(fv1.x, iv1.x, v0,i0,v1,i1,v2,i2,v3,i3);
        ins4s(fv1.y, iv1.y, v0,i0,v1,i1,v2,i2,v3,i3);
        ins4s(fv1.z, iv1.z, v0,i0,v1,i1,v2,i2,v3,i3);
        ins4s(fv1.w, iv1.w, v0,i0,v1,i1,v2,i2,v3,i3);
        if (lane < CC && valid[lane])
            ins4s(specs[r][lane], rps[lane], v0,i0,v1,i1,v2,i2,v3,i3);
        #pragma unroll
        for (int off = 16; off >= 1; off >>= 1) {
            float ov0 = __shfl_down_sync(0xffffffffu, v0, off);
            float ov1 = __shfl_down_sync(0xffffffffu, v1, off);
            float ov2 = __shfl_down_sync(0xffffffffu, v2, off);
            float ov3 = __shfl_down_sync(0xffffffffu, v3, off);
            int   oi0 = __shfl_down_sync(0xffffffffu, i0, off);
            int   oi1 = __shfl_down_sync(0xffffffffu, i1, off);
            int   oi2 = __shfl_down_sync(0xffffffffu, i2, off);
            int   oi3 = __shfl_down_sync(0xffffffffu, i3, off);
            if (lane < off) {
                ins4s(ov0, oi0, v0,i0,v1,i1,v2,i2,v3,i3);
                ins4s(ov1, oi1, v0,i0,v1,i1,v2,i2,v3,i3);
                ins4s(ov2, oi2, v0,i0,v1,i1,v2,i2,v3,i3);
                ins4s(ov3, oi3, v0,i0,v1,i1,v2,i2,v3,i3);
            }
        }
        if (lane == 0) {
            pos[r * 4 + 0] = i0; pos[r * 4 + 1] = i1;
            pos[r * 4 + 2] = i2; pos[r * 4 + 3] = i3;
        }
    }
    if (t == 128) {
        for (int k = 0; k < KK; k++) { pos[16 + k] = g_fp[b][k]; pos[20 + k] = g_bp[b][k]; }
        pos[24] = CC + 1;
    }
    __syncthreads();

    if (t < CC) {
        int p = pos[t];
        int ml = maxlen_s;
        p = p < 0 ? 0 : (p > ml ? ml : p);
        pos[t] = p;
        int s = -1;
        for (int c = 0; c < CC; c++) if (rps[c] == p) s = c;
        rowsrc[t] = s;
    }
    __syncthreads();

    for (int e = t; e < CC * CWN; e += 512) {
        int c = e >> 6, wc = e & 63;
        int s = rowsrc[c];
        vis[c][wc] = (s >= 0) ? visn[s][wc]
                              : memv[((size_t)b * MEMN + pos[c]) * CWN + wc];
    }
    __syncthreads();

    for (int k = wid; k < RR * CC; k += 16) {
        int c = k / RR, r = k % RR;
        float a0 = vis[c][lane], a1 = vis[c][lane + 32];
        float dt = a0 * q[r * 64 + lane] + a1 * q[r * 64 + 32 + lane];
        float vq = a0 * a0 + a1 * a1;
        #pragma unroll
        for (int off = 16; off >= 1; off >>= 1) {
            dt += __shfl_down_sync(0xffffffffu, dt, off);
            vq += __shfl_down_sync(0xffffffffu, vq, off);
        }
        if (lane == 0)
            sim[r][c] = dt * qn[r] / (sqrtf(vq) + EPS_F);
    }
    __syncthreads();

    if (wid < RR) {
        int r = wid;
        float v = (lane < CC) ? sim[r][lane] : -FLT_MAX;
        float mx = v;
        #pragma unroll
        for (int off = 16; off >= 1; off >>= 1)
            mx = fmaxf(mx, __shfl_xor_sync(0xffffffffu, mx, off));
        float e = (lane < CC) ? expf(v - mx) : 0.f;
        float sum = e;
        #pragma unroll
        for (int off = 16; off >= 1; off >>= 1)
            sum += __shfl_xor_sync(0xffffffffu, sum, off);
        if (lane < CC) swx[r][lane] = e / sum;
    }
    __syncthreads();

    if (t < DD) {
        int r = t >> 6, wc = t & 63;
        float o = 0.f;
        #pragma unroll 5
        for (int c = 0; c < CC; c++) o = fmaf(swx[r][c], vis[c][wc], o);
        out[b * RR * CWN + t] = o;
    }
}

// ============================================================================
extern "C" void kernel_launch(void* const* d_in, const int* in_sizes, int n_in,
                              void* d_out, int out_size) {
    const float* xi       = (const float*)d_in[0];
    const float* memory   = (const float*)d_in[1];
    const float* vism     = (const float*)d_in[2];
    const float* linkm    = (const float*)d_in[3];
    const float* rlinkm   = (const float*)d_in[4];
    const float* prec     = (const float*)d_in[5];
    const float* rw       = (const float*)d_in[6];
    const float* ww       = (const float*)d_in[7];
    const float* usage    = (const float*)d_in[8];
    const int*   rp       = (const int*)d_in[10];
    const float* W_rq     = (const float*)d_in[11];
    const float* b_rq     = (const float*)d_in[12];
    const float* W_wv     = (const float*)d_in[13];
    const float* b_wv     = (const float*)d_in[14];
    const float* W_ig     = (const float*)d_in[15];
    const float* b_ig     = (const float*)d_in[16];
    const float* W_wg     = (const float*)d_in[17];
    const float* b_wg     = (const float*)d_in[18];
    float* out = (float*)d_out;

    k0_q<<<BB * 8, 256>>>(xi, W_rq, b_rq);
    k2_scan<<<BB * NBLK + UMB + SETUPB, 256>>>(
        memory, usage, rp, xi,
        vism, linkm, rlinkm, prec, rw, ww,
        W_wv, b_wv, W_ig, b_ig, W_wg, b_wg);
    k3_finish<<<BB, 512>>>(memory, rp, out);
}

// round 15
// speedup vs baseline: 1.5843x; 1.5843x over previous
#include <cuda_runtime.h>
#include <float.h>
#include <math.h>
#include <stdint.h>

#define BB 8
#define DD 256
#define MEMN 131072
#define CWN 64
#define RR 4
#define KK 4
#define TKL 8
#define CC 25
#define DELTA_F 0.005f
#define EPS_F 1e-6f

#define NBLK 64
#define ROWS_PER_BLK (MEMN / NBLK)   // 2048
#define UMB 16
#define UMCH (MEMN / UMB)            // 8192
#define QB   64                      // q blocks (8 batches x 8 output chunks)
// grid layout: [0,64) q | [64,80) argmin | [80,88) setup | [88,600) scan

// ---------------- device scratch ----------------
__device__ float g_q[BB][DD];
__device__ float g_visnew[BB][CC][CWN];
__device__ float g_relnew[BB][CC];
__device__ int   g_fp[BB][KK];
__device__ int   g_bp[BB][KK];
__device__ __align__(16) float g_bv[BB][RR][NBLK][KK];
__device__ __align__(16) int   g_bi[BB][RR][NBLK][KK];
__device__ float g_uv[UMB];
__device__ int   g_ui[UMB];
__device__ int   g_qcnt = 0;         // q-ready counter; reset by k3 each call

// ---------------- helpers ----------------
__device__ __forceinline__ float d4(float4 a, float4 b, float acc) {
    acc = fmaf(a.x, b.x, acc);
    acc = fmaf(a.y, b.y, acc);
    acc = fmaf(a.z, b.z, acc);
    acc = fmaf(a.w, b.w, acc);
    return acc;
}

// top-4 insertion; larger value wins, ties -> lower index (jax.lax.top_k)
__device__ __forceinline__ void ins4s(float s, int m,
    float &v0, int &i0, float &v1, int &i1,
    float &v2, int &i2, float &v3, int &i3)
{
    if (!((s > v3) || (s == v3 && m < i3))) return;
    v3 = s; i3 = m;
    if ((v3 > v2) || (v3 == v2 && i3 < i2)) { float tv=v2; int ti=i2; v2=v3; i2=i3; v3=tv; i3=ti; }
    if ((v2 > v1) || (v2 == v1 && i2 < i1)) { float tv=v1; int ti=i1; v1=v2; i1=i2; v2=tv; i2=ti; }
    if ((v1 > v0) || (v1 == v0 && i1 < i0)) { float tv=v0; int ti=i0; v0=v1; i0=i1; v1=tv; i1=ti; }
}

__device__ __forceinline__ float sig_(float x) { return 1.f / (1.f + expf(-x)); }

// ============================================================================
// K2 (fused): 64 q-blocks + 16 argmin + 8 setup + 512 scan blocks.
// q-blocks are bid 0..63 (first-dispatched); scan blocks wait on g_qcnt.
// ============================================================================
__global__ void __launch_bounds__(256) k2_scan(
    const float* __restrict__ memv,
    const float* __restrict__ usage,
    const int*   __restrict__ rp,
    const float* __restrict__ xi,
    const float* __restrict__ W_rq, const float* __restrict__ b_rq,
    const float* __restrict__ visible_memory,
    const float* __restrict__ link_matrix,
    const float* __restrict__ rev_link_matrix,
    const float* __restrict__ precedence,
    const float* __restrict__ read_weights,
    const float* __restrict__ write_weights,
    const float* __restrict__ W_wv, const float* __restrict__ b_wv,
    const float* __restrict__ W_ig, const float* __restrict__ b_ig,
    const float* __restrict__ W_wg, const float* __restrict__ b_wg)
{
    int t = threadIdx.x;

    // ========================= Q BLOCKS (bid 0..63) =========================
    if (blockIdx.x < QB) {
        int b  = blockIdx.x >> 3;
        int oc = blockIdx.x & 7;
        int dc = t >> 5, o = t & 31;
        int og = oc * 32 + o;

        __shared__ float xs[DD];
        __shared__ float psum[8][32];

        xs[t] = xi[b * DD + t];
        __syncthreads();

        const float* W = W_rq + (size_t)(dc * 32) * 256 + og;
        const float* x = xs + dc * 32;
        float a0 = 0.f, a1 = 0.f, a2 = 0.f, a3 = 0.f;
        #pragma unroll
        for (int d = 0; d < 32; d += 4) {
            a0 = fmaf(x[d + 0], __ldg(&W[(d + 0) * 256]), a0);
            a1 = fmaf(x[d + 1], __ldg(&W[(d + 1) * 256]), a1);
            a2 = fmaf(x[d + 2], __ldg(&W[(d + 2) * 256]), a2);
            a3 = fmaf(x[d + 3], __ldg(&W[(d + 3) * 256]), a3);
        }
        psum[dc][o] = (a0 + a1) + (a2 + a3);
        __syncthreads();

        if (t < 32) {
            float s = b_rq[oc * 32 + t];
            #pragma unroll
            for (int c = 0; c < 8; c++) s += psum[c][t];
            g_q[b][oc * 32 + t] = s;
        }
        __syncthreads();
        if (t == 0) {
            __threadfence();
            atomicAdd(&g_qcnt, 1);
        }
        return;
    }

    // ========================= ARGMIN BLOCKS (64..79) =========================
    if (blockIdx.x < QB + UMB) {
        int ib = blockIdx.x - QB;
        __shared__ int   rp0[CC];
        __shared__ float svv[256];
        __shared__ int   sii[256];
        if (t < CC) rp0[t] = rp[t];
        __syncthreads();
        float bv = FLT_MAX; int bi = 0x7fffffff;
        int base = ib * UMCH;
        for (int j = t; j < UMCH; j += 256) {
            int idx = base + j;
            float v = __ldcs(&usage[idx]);
            bool masked = false;
            #pragma unroll
            for (int c = 0; c < CC; c++) masked |= (rp0[c] == idx);
            if (!masked && (v < bv || (v == bv && idx < bi))) { bv = v; bi = idx; }
        }
        svv[t] = bv; sii[t] = bi;
        __syncthreads();
        for (int s = 128; s > 0; s >>= 1) {
            if (t < s) {
                if (svv[t+s] < svv[t] || (svv[t+s] == svv[t] && sii[t+s] < sii[t])) {
                    svv[t] = svv[t+s]; sii[t] = sii[t+s];
                }
            }
            __syncthreads();
        }
        if (t == 0) { g_uv[ib] = svv[0]; g_ui[ib] = sii[0]; }
        return;
    }

    // ========================= SETUP BLOCKS (80..87) =========================
    if (blockIdx.x < QB + UMB + BB) {
        int b = blockIdx.x - (QB + UMB);

        __shared__ float xs[DD];
        __shared__ float pwv[4][CWN];
        __shared__ float pig[4][CC];
        __shared__ float pwg[32];
        __shared__ float wv_s[CWN];
        __shared__ float ig_s[CC];
        __shared__ float wg_s;
        __shared__ int   rp_s[CC];
        __shared__ float rw_s[CC], rel_s[CC], u_s[CC], imin_s[CC], wwnew_s[CC];
        __shared__ float minrel_s;
        __shared__ float fw_s[TKL], bw_s[TKL];

        xs[t] = xi[b * DD + t];
        if (t < CC) rp_s[t] = rp[b * CC + t];
        __syncthreads();

        bool hasE = (t >= 128 && t < 128 + CC);
        float e_rw = 0.f, e_ww = 0.f, e_rel = 0.f;
        if (hasE) {
            int p = rp_s[t - 128];
            e_rw  = __ldg(&read_weights [(size_t)b * MEMN + p]);
            e_ww  = __ldg(&write_weights[(size_t)b * MEMN + p]);
            e_rel = __ldg(&usage        [(size_t)b * MEMN + p]);
        }
        bool hasL = (t >= 160 && t < 160 + TKL);
        float l_wwm = 0.f, l_wwtp = 0.f, l_rwtp = 0.f, l_lk = 0.f, l_rl = 0.f, l_pr = 0.f;
        if (hasL) {
            int m = t - 160;
            int tp = rp_s[RR * KK + m];
            l_wwm  = __ldg(&write_weights  [(size_t)b * MEMN + m]);
            l_wwtp = __ldg(&write_weights  [(size_t)b * MEMN + tp]);
            l_rwtp = __ldg(&read_weights   [(size_t)b * MEMN + tp]);
            l_lk   = __ldg(&link_matrix    [((size_t)b * MEMN + m) * TKL + m]);
            l_rl   = __ldg(&rev_link_matrix[((size_t)b * MEMN + m) * TKL + m]);
            l_pr   = __ldg(&precedence     [b * TKL + m]);
        }

        {
            int o = t & 63, c = t >> 6;
            const float* W = W_wv + (size_t)(c * 64) * CWN + o;
            const float* x = xs + c * 64;
            float a0 = 0.f, a1 = 0.f, a2 = 0.f, a3 = 0.f;
            #pragma unroll 4
            for (int d = 0; d < 64; d += 4) {
                a0 = fmaf(x[d + 0], W[(d + 0) * CWN], a0);
                a1 = fmaf(x[d + 1], W[(d + 1) * CWN], a1);
                a2 = fmaf(x[d + 2], W[(d + 2) * CWN], a2);
                a3 = fmaf(x[d + 3], W[(d + 3) * CWN], a3);
            }
            pwv[c][o] = (a0 + a1) + (a2 + a3);
        }
        if (t < 100) {
            int o = t % CC, c = t / CC;
            const float* W = W_ig + (size_t)(c * 64) * CC + o;
            const float* x = xs + c * 64;
            float a0 = 0.f, a1 = 0.f;
            #pragma unroll 4
            for (int d = 0; d < 64; d += 2) {
                a0 = fmaf(x[d + 0], W[(d + 0) * CC], a0);
                a1 = fmaf(x[d + 1], W[(d + 1) * CC], a1);
            }
            pig[c][o] = a0 + a1;
        }
        if (t >= 100 && t < 132) {
            int u = t - 100;
            float a = 0.f;
            #pragma unroll
            for (int d = 0; d < 8; d++)
                a = fmaf(xs[u * 8 + d], __ldg(&W_wg[u * 8 + d]), a);
            pwg[u] = a;
        }
        if (hasE) {
            int c = t - 128;
            rw_s[c]  = e_rw;
            rel_s[c] = e_rel;
            u_s[c]   = (e_rw + e_ww > DELTA_F) ? 1.f : 0.f;
        }
        __syncthreads();

        if (t < CWN) {
            wv_s[t] = b_wv[t] + ((pwv[0][t] + pwv[1][t]) + (pwv[2][t] + pwv[3][t]));
        } else if (t < CWN + CC) {
            int o = t - CWN;
            ig_s[o] = sig_(b_ig[o] + ((pig[0][o] + pig[1][o]) + (pig[2][o] + pig[3][o])));
        } else if (t == CWN + CC) {
            float s = b_wg[0];
            #pragma unroll
            for (int u = 0; u < 32; u++) s += pwg[u];
            wg_s = sig_(s);
        } else if (t == 96) {
            float mn = rel_s[0];
            for (int c = 1; c < CC; c++) mn = fminf(mn, rel_s[c]);
            minrel_s = mn;
        }
        __syncthreads();

        if (t < CC) {
            float Imin = (rel_s[t] == minrel_s) ? 1.f : 0.f;
            imin_s[t] = Imin;
            float u = u_s[t], rel = rel_s[t];
            g_relnew[b][t] = (1.f - rel) * u + rel * (1.f - u);
            wwnew_s[t] = wg_s * (ig_s[t] * rw_s[t] + (1.f - ig_s[t]) * Imin);
        }
        __syncthreads();

        for (int e = t; e < CC * CWN; e += 256) {
            int c = e / CWN, k = e % CWN;
            float v = visible_memory[((size_t)b * CC + c) * CWN + k];
            g_visnew[b][c][k] = v * (1.f - imin_s[c]) + wwnew_s[c] * wv_s[k];
        }

        if (hasL) {
            int m = t - 160;
            float wwf = l_wwm;
            for (int c = 0; c < CC; c++) if (rp_s[c] == m) wwf = wwnew_s[c];
            int tp = rp_s[RR * KK + m];
            float tw = l_wwtp;
            for (int c = 0; c < CC; c++) if (rp_s[c] == tp) tw = wwnew_s[c];
            float pd = 0.f;
            for (int j = 0; j < TKL; j++)
                if (rp_s[RR * KK + j] == m) pd = __ldg(&precedence[b * TKL + j]);
            float Ld = (1.f - wwf) * l_lk + wwf * l_pr;
            float Rd = (1.f - tw ) * l_rl + tw  * pd;
            fw_s[m] = Ld * l_rwtp;
            bw_s[m] = Rd * l_rwtp;
        }
        __syncthreads();

        if (t == 0) {
            bool used[TKL];
            for (int m = 0; m < TKL; m++) used[m] = false;
            for (int k = 0; k < KK; k++) {
                int best = -1;
                for (int m = 0; m < TKL; m++)
                    if (!used[m] && (best < 0 || fw_s[m] > fw_s[best])) best = m;
                used[best] = true;
                g_fp[b][k] = best;
            }
            for (int m = 0; m < TKL; m++) used[m] = false;
            for (int k = 0; k < KK; k++) {
                int best = -1;
                for (int m = 0; m < TKL; m++)
                    if (!used[m] && (best < 0 || bw_s[m] > bw_s[best])) best = m;
                used[best] = true;
                g_bp[b][k] = best;
            }
        }
        return;
    }

    // ========================= SCAN BLOCKS (88..599) =========================
    int idx = blockIdx.x - (QB + UMB + BB);
    int b   = idx >> 6;
    int blk = idx & 63;
    int rowbase = blk * ROWS_PER_BLK;
    int lane = t & 31, w = t >> 5;
    int sub = lane & 7, grp = lane >> 3;

    __shared__ int   ns;
    __shared__ int   srow[CC];
    __shared__ float msv[RR][128];
    __shared__ int   msi[RR][128];
    if (t == 0) ns = 0;
    __syncthreads();
    if (t < CC) {
        int p = rp[b * CC + t];
        if (p >= rowbase && p < rowbase + ROWS_PER_BLK) {
            int k = atomicAdd(&ns, 1);
            srow[k] = p;
        }
    }

    // wait for q-blocks (bid 0..63 dispatched first; they never wait)
    if (t == 0) {
        while (atomicAdd(&g_qcnt, 0) < QB) __nanosleep(64);
    }
    __syncthreads();

    // q in registers (written by q-blocks)
    float4 q0[RR], q1[RR];
    #pragma unroll
    for (int r = 0; r < RR; r++) {
        q0[r] = *(const float4*)&g_q[b][r * CWN + sub * 4];
        q1[r] = *(const float4*)&g_q[b][r * CWN + 32 + sub * 4];
    }
    int nspec = ns;

    float tv0 = -FLT_MAX, tv1 = -FLT_MAX, tv2 = -FLT_MAX, tv3 = -FLT_MAX;
    int   ti0 = 0x7fffffff, ti1 = 0x7fffffff, ti2 = 0x7fffffff, ti3 = 0x7fffffff;

    const float4* basep = (const float4*)(memv + (size_t)b * MEMN * CWN);
    #pragma unroll 2
    for (int it = 0; it < ROWS_PER_BLK / 32; it++) {
        int row = rowbase + it * 32 + w * 4 + grp;
        const float4* p = basep + (size_t)row * 16;
        float4 a0 = __ldcs(p + sub);
        float4 a1 = __ldcs(p + 8 + sub);

        float sq = d4(a0, a0, 0.f); sq = d4(a1, a1, sq);
        float dt0 = d4(a0, q0[0], 0.f); dt0 = d4(a1, q1[0], dt0);
        float dt1 = d4(a0, q0[1], 0.f); dt1 = d4(a1, q1[1], dt1);
        float dt2 = d4(a0, q0[2], 0.f); dt2 = d4(a1, q1[2], dt2);
        float dt3 = d4(a0, q0[3], 0.f); dt3 = d4(a1, q1[3], dt3);

        float v0 = fmaf(2.f, dt0, -sq);
        float v1 = fmaf(2.f, dt1, -sq);
        float v2 = fmaf(2.f, dt2, -sq);
        float v3 = fmaf(2.f, dt3, -sq);

        #pragma unroll
        for (int m = 4; m >= 1; m >>= 1) {
            v0 += __shfl_xor_sync(0xffffffffu, v0, m);
            v1 += __shfl_xor_sync(0xffffffffu, v1, m);
            v2 += __shfl_xor_sync(0xffffffffu, v2, m);
            v3 += __shfl_xor_sync(0xffffffffu, v3, m);
        }

        if (sub < RR) {
            float s = (sub == 0) ? v0 : (sub == 1) ? v1 : (sub == 2) ? v2 : v3;
            for (int j = 0; j < nspec; j++) if (srow[j] == row) s = -FLT_MAX;
            ins4s(s, row, tv0, ti0, tv1, ti1, tv2, ti2, tv3, ti3);
        }
    }

    if (sub < RR) {
        int slot = w * 16 + grp * 4;
        msv[sub][slot + 0] = tv0; msi[sub][slot + 0] = ti0;
        msv[sub][slot + 1] = tv1; msi[sub][slot + 1] = ti1;
        msv[sub][slot + 2] = tv2; msi[sub][slot + 2] = ti2;
        msv[sub][slot + 3] = tv3; msi[sub][slot + 3] = ti3;
    }
    __syncthreads();

    if (t < RR) {
        float v0 = -FLT_MAX, v1 = -FLT_MAX, v2 = -FLT_MAX, v3 = -FLT_MAX;
        int   i0 = 0x7fffffff, i1 = 0x7fffffff, i2 = 0x7fffffff, i3 = 0x7fffffff;
        for (int j = 0; j < 128; j++)
            ins4s(msv[t][j], msi[t][j], v0, i0, v1, i1, v2, i2, v3, i3);
        g_bv[b][t][blk][0] = v0; g_bi[b][t][blk][0] = i0;
        g_bv[b][t][blk][1] = v1; g_bi[b][t][blk][1] = i1;
        g_bv[b][t][blk][2] = v2; g_bi[b][t][blk][2] = i2;
        g_bv[b][t][blk][3] = v3; g_bi[b][t][blk][3] = i3;
    }
}

// ============================================================================
// K3: fully warp-parallel finish (R10/R12 proven). Resets g_qcnt for the
//     next graph replay (runs strictly after k2 consumed it).
// ============================================================================
__global__ void __launch_bounds__(512) k3_finish(
    const float* __restrict__ memv,
    const int*   __restrict__ rp,
    float* __restrict__ out)
{
    int b = blockIdx.x;
    int t = threadIdx.x;
    int lane = t & 31, wid = t >> 5;

    if (b == 0 && t == 0) g_qcnt = 0;   // reset for next launch

    __shared__ float q[DD];
    __shared__ float visn[CC][CWN];
    __shared__ float qn[RR];
    __shared__ int   rps[CC];
    __shared__ int   rp0s[CC];
    __shared__ int   valid[CC];
    __shared__ float specs[RR][CC];
    __shared__ int   pos[CC];
    __shared__ int   maxlen_s;
    __shared__ int   rowsrc[CC];
    __shared__ float vis[CC][CWN];
    __shared__ float sim[RR][CC];
    __shared__ float swx[RR][CC];

    if (t < DD) q[t] = g_q[b][t];
    if (t >= 256 && t < 256 + CC) rps[t - 256] = rp[b * CC + (t - 256)];
    if (t >= 288 && t < 288 + CC) rp0s[t - 288] = rp[t - 288];
    for (int e = t; e < CC * CWN; e += 512)
        visn[e >> 6][e & 63] = g_visnew[b][e >> 6][e & 63];
    __syncthreads();

    if (wid < RR) {
        float a0 = q[wid * 64 + lane], a1 = q[wid * 64 + 32 + lane];
        float s = a0 * a0 + a1 * a1;
        #pragma unroll
        for (int off = 16; off >= 1; off >>= 1)
            s += __shfl_down_sync(0xffffffffu, s, off);
        if (lane == 0) qn[wid] = 1.f / (sqrtf(s) + EPS_F);
    }
    if (wid < 15) {
        for (int k = wid; k < RR * CC; k += 15) {
            int c = k / RR, r = k % RR;
            float a0 = visn[c][lane], a1 = visn[c][lane + 32];
            float dt = a0 * q[r * 64 + lane] + a1 * q[r * 64 + 32 + lane];
            float sq = a0 * a0 + a1 * a1;
            #pragma unroll
            for (int off = 16; off >= 1; off >>= 1) {
                dt += __shfl_down_sync(0xffffffffu, dt, off);
                sq += __shfl_down_sync(0xffffffffu, sq, off);
            }
            if (lane == 0) specs[r][c] = 2.f * dt - sq;
        }
    } else {
        float cv_ = FLT_MAX; int cix = 0x7fffffff;
        if (lane < UMB) { cv_ = g_uv[lane]; cix = g_ui[lane]; }
        if (lane < CC) {
            int p0 = rp0s[lane];
            bool last = true;
            for (int c2 = lane + 1; c2 < CC; c2++) if (rp0s[c2] == p0) last = false;
            if (last) {
                float v = g_relnew[0][lane];
                if (v < cv_ || (v == cv_ && p0 < cix)) { cv_ = v; cix = p0; }
            }
        }
        #pragma unroll
        for (int off = 16; off >= 1; off >>= 1) {
            float ov = __shfl_down_sync(0xffffffffu, cv_, off);
            int   oi = __shfl_down_sync(0xffffffffu, cix, off);
            if (lane < off && (ov < cv_ || (ov == cv_ && oi < cix))) { cv_ = ov; cix = oi; }
        }
        if (lane == 0) maxlen_s = cix;
    }
    if (t >= 448 && t < 448 + CC) {
        int c = t - 448;
        int v = 1;
        for (int c2 = c + 1; c2 < CC; c2++) if (rps[c2] == rps[c]) v = 0;
        valid[c] = v;
    }
    __syncthreads();

    if (wid < RR) {
        int r = wid;
        float v0 = -FLT_MAX, v1 = -FLT_MAX, v2 = -FLT_MAX, v3 = -FLT_MAX;
        int   i0 = 0x7fffffff, i1 = 0x7fffffff, i2 = 0x7fffffff, i3 = 0x7fffffff;
        const float4* pv = (const float4*)&g_bv[b][r][0][0];
        const int4*   pi = (const int4*)&g_bi[b][r][0][0];
        float4 fv0 = pv[2 * lane], fv1 = pv[2 * lane + 1];
        int4   iv0 = pi[2 * lane], iv1 = pi[2 * lane + 1];
        ins4s(fv0.x, iv0.x, v0,i0,v1,i1,v2,i2,v3,i3);
        ins4s(fv0.y, iv0.y, v0,i0,v1,i1,v2,i2,v3,i3);
        ins4s(fv0.z, iv0.z, v0,i0,v1,i1,v2,i2,v3,i3);
        ins4s(fv0.w, iv0.w, v0,i0,v1,i1,v2,i2,v3,i3);
        ins4s(fv1.x, iv1.x, v0,i0,v1,i1,v2,i2,v3,i3);
        ins4s(fv1.y, iv1.y, v0,i0,v1,i1,v2,i2,v3,i3);
        ins4s(fv1.z, iv1.z, v0,i0,v1,i1,v2,i2,v3,i3);
        ins4s(fv1.w, iv1.w, v0,i0,v1,i1,v2,i2,v3,i3);
        if (lane < CC && valid[lane])
            ins4s(specs[r][lane], rps[lane], v0,i0,v1,i1,v2,i2,v3,i3);
        #pragma unroll
        for (int off = 16; off >= 1; off >>= 1) {
            float ov0 = __shfl_down_sync(0xffffffffu, v0, off);
            float ov1 = __shfl_down_sync(0xffffffffu, v1, off);
            float ov2 = __shfl_down_sync(0xffffffffu, v2, off);
            float ov3 = __shfl_down_sync(0xffffffffu, v3, off);
            int   oi0 = __shfl_down_sync(0xffffffffu, i0, off);
            int   oi1 = __shfl_down_sync(0xffffffffu, i1, off);
            int   oi2 = __shfl_down_sync(0xffffffffu, i2, off);
            int   oi3 = __shfl_down_sync(0xffffffffu, i3, off);
            if (lane < off) {
                ins4s(ov0, oi0, v0,i0,v1,i1,v2,i2,v3,i3);
                ins4s(ov1, oi1, v0,i0,v1,i1,v2,i2,v3,i3);
                ins4s(ov2, oi2, v0,i0,v1,i1,v2,i2,v3,i3);
                ins4s(ov3, oi3, v0,i0,v1,i1,v2,i2,v3,i3);
            }
        }
        if (lane == 0) {
            pos[r * 4 + 0] = i0; pos[r * 4 + 1] = i1;
            pos[r * 4 + 2] = i2; pos[r * 4 + 3] = i3;
        }
    }
    if (t == 128) {
        for (int k = 0; k < KK; k++) { pos[16 + k] = g_fp[b][k]; pos[20 + k] = g_bp[b][k]; }
        pos[24] = CC + 1;
    }
    __syncthreads();

    if (t < CC) {
        int p = pos[t];
        int ml = maxlen_s;
        p = p < 0 ? 0 : (p > ml ? ml : p);
        pos[t] = p;
        int s = -1;
        for (int c = 0; c < CC; c++) if (rps[c] == p) s = c;
        rowsrc[t] = s;
    }
    __syncthreads();

    for (int e = t; e < CC * CWN; e += 512) {
        int c = e >> 6, wc = e & 63;
        int s = rowsrc[c];
        vis[c][wc] = (s >= 0) ? visn[s][wc]
                              : memv[((size_t)b * MEMN + pos[c]) * CWN + wc];
    }
    __syncthreads();

    for (int k = wid; k < RR * CC; k += 16) {
        int c = k / RR, r = k % RR;
        float a0 = vis[c][lane], a1 = vis[c][lane + 32];
        float dt = a0 * q[r * 64 + lane] + a1 * q[r * 64 + 32 + lane];
        float vq = a0 * a0 + a1 * a1;
        #pragma unroll
        for (int off = 16; off >= 1; off >>= 1) {
            dt += __shfl_down_sync(0xffffffffu, dt, off);
            vq += __shfl_down_sync(0xffffffffu, vq, off);
        }
        if (lane == 0)
            sim[r][c] = dt * qn[r] / (sqrtf(vq) + EPS_F);
    }
    __syncthreads();

    if (wid < RR) {
        int r = wid;
        float v = (lane < CC) ? sim[r][lane] : -FLT_MAX;
        float mx = v;
        #pragma unroll
        for (int off = 16; off >= 1; off >>= 1)
            mx = fmaxf(mx, __shfl_xor_sync(0xffffffffu, mx, off));
        float e = (lane < CC) ? expf(v - mx) : 0.f;
        float sum = e;
        #pragma unroll
        for (int off = 16; off >= 1; off >>= 1)
            sum += __shfl_xor_sync(0xffffffffu, sum, off);
        if (lane < CC) swx[r][lane] = e / sum;
    }
    __syncthreads();

    if (t < DD) {
        int r = t >> 6, wc = t & 63;
        float o = 0.f;
        #pragma unroll 5
        for (int c = 0; c < CC; c++) o = fmaf(swx[r][c], vis[c][wc], o);
        out[b * RR * CWN + t] = o;
    }
}

// ============================================================================
extern "C" void kernel_launch(void* const* d_in, const int* in_sizes, int n_in,
                              void* d_out, int out_size) {
    const float* xi       = (const float*)d_in[0];
    const float* memory   = (const float*)d_in[1];
    const float* vism     = (const float*)d_in[2];
    const float* linkm    = (const float*)d_in[3];
    const float* rlinkm   = (const float*)d_in[4];
    const float* prec     = (const float*)d_in[5];
    const float* rw       = (const float*)d_in[6];
    const float* ww       = (const float*)d_in[7];
    const float* usage    = (const float*)d_in[8];
    const int*   rp       = (const int*)d_in[10];
    const float* W_rq     = (const float*)d_in[11];
    const float* b_rq     = (const float*)d_in[12];
    const float* W_wv     = (const float*)d_in[13];
    const float* b_wv     = (const float*)d_in[14];
    const float* W_ig     = (const float*)d_in[15];
    const float* b_ig     = (const float*)d_in[16];
    const float* W_wg     = (const float*)d_in[17];
    const float* b_wg     = (const float*)d_in[18];
    float* out = (float*)d_out;

    k2_scan<<<QB + UMB + BB + BB * NBLK, 256>>>(
        memory, usage, rp, xi, W_rq, b_rq,
        vism, linkm, rlinkm, prec, rw, ww,
        W_wv, b_wv, W_ig, b_ig, W_wg, b_wg);
    k3_finish<<<BB, 512>>>(memory, rp, out);
}